// round 13
// baseline (speedup 1.0000x reference)
#include <cuda_runtime.h>
#include <cstdint>

// VectorQuantizer: x [32,64,64,64] fp32, emb [512,64] fp32.
// Per pixel: argmin_k fl(fl(xsq+esq[k]) - 2*dot), dot = sequential ascending-d FMA chain.
// Then out[b,:,h,w] = emb[argmin].
//
// Round 12: binder identified as LDS *instruction count* (scalar uint64 loads never
// vectorized -> LSU-saturated: R11 L1=93.9%, fma=26.8%). Fix: all inner-loop smem
// reads via ulonglong2 (ld.shared.v2.u64 = LDS.128, components are native 64-bit
// regs -> zero repack MOVs into fma.rn.f32x2).
//   xs[d][pp] = {x[2pp], x[2pp+1]}   natural pixel-pair packing (no dup needed)
//   es[d][k]  = {e[k], e[k]}         pre-duplicated at staging (coalesced gmem)
// Thread tile: 4 pixel-pairs (8 px) x 8 codes = 32 FFMA2 per d, 6 LDS.128 per d.
// Block 256 thr, tile 128 px x 128 codes, NKT=4, 2 blocks/SM (16 warps).

#define KCODES 512
#define DDIM   64
#define PT     128
#define KT     128
#define NKT    (KCODES / KT)   // 4
#define NTHR   256

// dynamic smem layout (bytes)
#define XS_OFF     0                          // float2 xs[64][64]   = 32768
#define ES_OFF     32768                      // float2 es[64][128]  = 65536 (dup {e,e})
#define XSQ_OFF    (ES_OFF + 65536)           // float xsq[128]      = 512
#define ESQ_OFF    (XSQ_OFF + 512)            // float esq_all[512]  = 2048
#define WIDX_OFF   (ESQ_OFF + 2048)           // int   widx[128]     = 512
#define SMEM_BYTES (WIDX_OFF + 512)           // 101376 x2 = 202752 <= 228KB/SM
// reduction arrays overlay xs after the mainloop:
#define RVAL_OFF   XS_OFF                     // float red_val[128][16] = 8192
#define RIDX_OFF   (XS_OFF + 8192)            // int   red_idx[128][16] = 8192

#define FMA2(acc, a, b) \
    asm("fma.rn.f32x2 %0, %1, %2, %0;" : "+l"(acc) : "l"(a), "l"(b))

__global__ __launch_bounds__(NTHR, 2)
void vq_kernel(const float* __restrict__ x,
               const float* __restrict__ emb,
               float* __restrict__ out,
               int HW, int CHW)
{
    extern __shared__ char smem_raw[];
    float2* xs      = (float2*)(smem_raw + XS_OFF);    // xs[d*64 + pp]
    float2* es      = (float2*)(smem_raw + ES_OFF);    // es[d*128 + k] = {e,e}
    float*  xsq     = (float*)(smem_raw + XSQ_OFF);
    float*  esq_all = (float*)(smem_raw + ESQ_OFF);
    int*    widx    = (int*)(smem_raw + WIDX_OFF);
    float*  red_val = (float*)(smem_raw + RVAL_OFF);
    int*    red_idx = (int*)(smem_raw + RIDX_OFF);

    const int t   = threadIdx.x;
    const int n0  = blockIdx.x * PT;
    const int b   = n0 >> 12;          // HW = 4096; tiles never cross batch
    const int hw0 = n0 & 4095;

    // ---- stage x tile as pixel pairs (coalesced float2) ----
    const float2* xb2 = (const float2*)(x + (size_t)b * CHW + hw0);
    #pragma unroll
    for (int it = 0; it < (DDIM * (PT / 2)) / NTHR; ++it) {   // 16 iters
        int lin = it * NTHR + t;
        int c  = lin >> 6;
        int pp = lin & 63;
        xs[c * 64 + pp] = xb2[c * (HW / 2) + pp];
    }

    // ---- esq for ALL 512 codes, once (L2-hot; ascending d, rounded mul then add) ----
    #pragma unroll
    for (int kk = 0; kk < 2; ++kk) {
        int k = t * 2 + kk;
        const float4* er = (const float4*)(emb + (size_t)k * DDIM);
        float s = 0.0f;
        #pragma unroll
        for (int q = 0; q < DDIM / 4; ++q) {
            float4 v = er[q];
            s = __fadd_rn(s, __fmul_rn(v.x, v.x));
            s = __fadd_rn(s, __fmul_rn(v.y, v.y));
            s = __fadd_rn(s, __fmul_rn(v.z, v.z));
            s = __fadd_rn(s, __fmul_rn(v.w, v.w));
        }
        esq_all[k] = s;
    }
    __syncthreads();

    // ---- ||x||^2 per pixel (ascending d, rounded mul then add) ----
    if (t < PT) {
        int pp = t >> 1, comp = t & 1;
        float s = 0.0f;
        #pragma unroll 8
        for (int d = 0; d < DDIM; ++d) {
            float v = ((const float*)&xs[d * 64 + pp])[comp];
            s = __fadd_rn(s, __fmul_rn(v, v));
        }
        xsq[t] = s;
    }

    // warp mapping: 8 pxg x 4 kgg per warp (intra-warp dedup: 256B x + 256B e per d)
    const int pxg = (t & 7) | ((t >> 4) & 8);   // 0..15, 4 pixel-pairs (8 px) each
    const int kgg = (t >> 3) & 15;              // 0..15, 8 codes each

    float best[8];
    int   bidx[8];
    #pragma unroll
    for (int i = 0; i < 8; ++i) { best[i] = 3.4e38f; bidx[i] = 0; }

    for (int kt = 0; kt < NKT; ++kt) {
        __syncthreads();   // xsq ready (1st iter) / protect es reuse
        // ---- stage e tile DUPLICATED, gmem reads coalesced float4 ----
        #pragma unroll
        for (int it = 0; it < (KT * DDIM / 4) / NTHR; ++it) {  // 8 iters
            int lin = it * NTHR + t;          // 0..2047
            int k   = lin >> 4;               // 0..127
            int d4  = (lin & 15) * 4;         // consecutive lanes -> consecutive d4
            float4 ev = *(const float4*)(emb + (size_t)(kt * KT + k) * DDIM + d4);
            es[(d4 + 0) * 128 + k] = make_float2(ev.x, ev.x);
            es[(d4 + 1) * 128 + k] = make_float2(ev.y, ev.y);
            es[(d4 + 2) * 128 + k] = make_float2(ev.z, ev.z);
            es[(d4 + 3) * 128 + k] = make_float2(ev.w, ev.w);
        }
        __syncthreads();

        // ---- mainloop: 6 x LDS.128 (ld.shared.v2.u64) + 32 FFMA2 per d, zero MOVs ----
        uint64_t acc[4][8];
        #pragma unroll
        for (int pp = 0; pp < 4; ++pp)
            #pragma unroll
            for (int j = 0; j < 8; ++j) acc[pp][j] = 0ull;

        const ulonglong2* xsv = (const ulonglong2*)((const uint64_t*)xs + pxg * 4);
        const ulonglong2* esv = (const ulonglong2*)((const uint64_t*)es + kgg * 8);

        #pragma unroll 2
        for (int d = 0; d < DDIM; ++d) {
            const ulonglong2* xp = xsv + d * 32;   // 64 uint64 per d-row = 32 ull2
            const ulonglong2* ep = esv + d * 64;   // 128 uint64 per d-row = 64 ull2
            ulonglong2 xa = xp[0], xb_ = xp[1];           // 4 pixel-pairs
            ulonglong2 ea = ep[0], eb = ep[1], ec = ep[2], ed = ep[3];  // 8 dup codes
            uint64_t x0 = xa.x, x1 = xa.y, x2 = xb_.x, x3 = xb_.y;
            uint64_t e0 = ea.x, e1 = ea.y, e2 = eb.x, e3 = eb.y;
            uint64_t e4 = ec.x, e5 = ec.y, e6 = ed.x, e7 = ed.y;
            FMA2(acc[0][0], x0, e0); FMA2(acc[0][1], x0, e1);
            FMA2(acc[0][2], x0, e2); FMA2(acc[0][3], x0, e3);
            FMA2(acc[0][4], x0, e4); FMA2(acc[0][5], x0, e5);
            FMA2(acc[0][6], x0, e6); FMA2(acc[0][7], x0, e7);
            FMA2(acc[1][0], x1, e0); FMA2(acc[1][1], x1, e1);
            FMA2(acc[1][2], x1, e2); FMA2(acc[1][3], x1, e3);
            FMA2(acc[1][4], x1, e4); FMA2(acc[1][5], x1, e5);
            FMA2(acc[1][6], x1, e6); FMA2(acc[1][7], x1, e7);
            FMA2(acc[2][0], x2, e0); FMA2(acc[2][1], x2, e1);
            FMA2(acc[2][2], x2, e2); FMA2(acc[2][3], x2, e3);
            FMA2(acc[2][4], x2, e4); FMA2(acc[2][5], x2, e5);
            FMA2(acc[2][6], x2, e6); FMA2(acc[2][7], x2, e7);
            FMA2(acc[3][0], x3, e0); FMA2(acc[3][1], x3, e1);
            FMA2(acc[3][2], x3, e2); FMA2(acc[3][3], x3, e3);
            FMA2(acc[3][4], x3, e4); FMA2(acc[3][5], x3, e5);
            FMA2(acc[3][6], x3, e6); FMA2(acc[3][7], x3, e7);
        }

        // ---- fold: s = fmaf(-2, dot, fl(xsq+esq)); ascending k keeps lowest idx ----
        #pragma unroll
        for (int j = 0; j < 8; ++j) {
            int   k  = kt * KT + kgg * 8 + j;
            float eq = esq_all[k];
            #pragma unroll
            for (int pp = 0; pp < 4; ++pp) {
                float lo, hi;
                asm("mov.b64 {%0, %1}, %2;" : "=f"(lo), "=f"(hi) : "l"(acc[pp][j]));
                float t0 = __fadd_rn(xsq[pxg * 8 + 2 * pp], eq);
                float t1 = __fadd_rn(xsq[pxg * 8 + 2 * pp + 1], eq);
                float s0 = __fmaf_rn(-2.0f, lo, t0);
                float s1 = __fmaf_rn(-2.0f, hi, t1);
                if (s0 < best[2 * pp])     { best[2 * pp]     = s0; bidx[2 * pp]     = k; }
                if (s1 < best[2 * pp + 1]) { best[2 * pp + 1] = s1; bidx[2 * pp + 1] = k; }
            }
        }
    }

    // ---- cross-thread argmin reduction (red arrays overlay xs; xs dead now) ----
    __syncthreads();
    #pragma unroll
    for (int i = 0; i < 8; ++i) {
        red_val[(pxg * 8 + i) * 16 + kgg] = best[i];
        red_idx[(pxg * 8 + i) * 16 + kgg] = bidx[i];
    }
    __syncthreads();
    if (t < PT) {
        float bv = red_val[t * 16 + 0];
        int   bi = red_idx[t * 16 + 0];
        #pragma unroll
        for (int g = 1; g < 16; ++g) {
            float v  = red_val[t * 16 + g];
            int   id = red_idx[t * 16 + g];
            if (v < bv || (v == bv && id < bi)) { bv = v; bi = id; }
        }
        widx[t] = bi;
    }
    __syncthreads();

    // ---- gather + write out[b, c, hw0+p] = emb[widx[p]][c] ----
    float* ob = out + (size_t)b * CHW + hw0;
    #pragma unroll
    for (int it = 0; it < (DDIM * PT) / NTHR; ++it) {
        int lin = it * NTHR + t;
        int c = lin >> 7;
        int p = lin & 127;
        ob[c * HW + p] = emb[(size_t)widx[p] * DDIM + c];
    }
}

extern "C" void kernel_launch(void* const* d_in, const int* in_sizes, int n_in,
                              void* d_out, int out_size)
{
    const float* x   = (const float*)d_in[0];   // [32, 64, 64, 64]
    const float* emb = (const float*)d_in[1];   // [512, 64]
    float* out = (float*)d_out;

    const int HW  = 64 * 64;             // 4096
    const int CHW = DDIM * HW;           // 262144
    const int N   = in_sizes[0] / DDIM;  // 131072 pixels

    cudaFuncSetAttribute(vq_kernel, cudaFuncAttributeMaxDynamicSharedMemorySize,
                         SMEM_BYTES);

    dim3 grid(N / PT);                   // 1024
    dim3 block(NTHR);
    vq_kernel<<<grid, block, SMEM_BYTES>>>(x, emb, out, HW, CHW);
}

// round 14
// speedup vs baseline: 1.3000x; 1.3000x over previous
#include <cuda_runtime.h>
#include <cstdint>

// VectorQuantizer: x [32,64,64,64] fp32, emb [512,64] fp32.
// Per pixel: argmin_k fl(fl(xsq+esq[k]) - 2*dot), dot = sequential ascending-d FMA chain.
// Then out[b,:,h,w] = emb[argmin].
//
// Round 14: break the ~50 FMA/cyc/SM latency wall seen in ALL prior rounds.
//   * 3 blocks/SM x 256 thr = 24 warps (6/SMSP)  -- launch_bounds(256,3), 85-reg cap
//   * thread tile 4 pixel-pairs x 4 codes: acc = 32 regs -> total ~75 regs, NO spills
//   * all inner-loop smem reads are ulonglong2 (LDS.128): 4 loads per 16 FFMA2
//   * zero inner-loop MOVs: es pre-duplicated {e,e}, xs natural pixel pairs
//   * block tile 128 px x 64 codes, NKT=8; esq for all 512 codes computed once
// Per SMSP-d: pipe 192 cyc vs LSU 96, issue 120 -> fma-pipe binder, 2x headroom.

#define KCODES 512
#define DDIM   64
#define PT     128
#define KT     64
#define NKT    (KCODES / KT)   // 8
#define NTHR   256

// dynamic smem layout (bytes)
#define XS_OFF     0                          // float2 xs[64][64]  = 32768
#define ES_OFF     32768                      // float2 es[64][64]  = 32768 (dup {e,e})
#define XSQ_OFF    (ES_OFF + 32768)           // float xsq[128]     = 512
#define ESQ_OFF    (XSQ_OFF + 512)            // float esq_all[512] = 2048
#define WIDX_OFF   (ESQ_OFF + 2048)           // int   widx[128]    = 512
#define SMEM_BYTES (WIDX_OFF + 512)           // 68608 x3 = 205824 <= 228KB/SM
// reduction arrays overlay xs after the mainloop (16KB <= 32KB xs region):
#define RVAL_OFF   XS_OFF                     // float red_val[128][16] = 8192
#define RIDX_OFF   (XS_OFF + 8192)            // int   red_idx[128][16] = 8192

#define FMA2(acc, a, b) \
    asm("fma.rn.f32x2 %0, %1, %2, %0;" : "+l"(acc) : "l"(a), "l"(b))

__global__ __launch_bounds__(NTHR, 3)
void vq_kernel(const float* __restrict__ x,
               const float* __restrict__ emb,
               float* __restrict__ out,
               int HW, int CHW)
{
    extern __shared__ char smem_raw[];
    float2* xs      = (float2*)(smem_raw + XS_OFF);    // xs[d*64 + pp] = {x[2pp], x[2pp+1]}
    float2* es      = (float2*)(smem_raw + ES_OFF);    // es[d*64 + k]  = {e[k], e[k]}
    float*  xsq     = (float*)(smem_raw + XSQ_OFF);
    float*  esq_all = (float*)(smem_raw + ESQ_OFF);
    int*    widx    = (int*)(smem_raw + WIDX_OFF);
    float*  red_val = (float*)(smem_raw + RVAL_OFF);
    int*    red_idx = (int*)(smem_raw + RIDX_OFF);

    const int t   = threadIdx.x;
    const int n0  = blockIdx.x * PT;
    const int b   = n0 >> 12;          // HW = 4096; tiles never cross batch
    const int hw0 = n0 & 4095;

    // ---- stage x tile as pixel pairs (coalesced float2) ----
    const float2* xb2 = (const float2*)(x + (size_t)b * CHW + hw0);
    #pragma unroll
    for (int it = 0; it < (DDIM * (PT / 2)) / NTHR; ++it) {   // 16 iters
        int lin = it * NTHR + t;
        int c  = lin >> 6;
        int pp = lin & 63;
        xs[c * 64 + pp] = xb2[c * (HW / 2) + pp];
    }

    // ---- esq for ALL 512 codes, once (L2-hot; ascending d, rounded mul then add) ----
    #pragma unroll
    for (int kk = 0; kk < 2; ++kk) {
        int k = t * 2 + kk;
        const float4* er = (const float4*)(emb + (size_t)k * DDIM);
        float s = 0.0f;
        #pragma unroll
        for (int q = 0; q < DDIM / 4; ++q) {
            float4 v = er[q];
            s = __fadd_rn(s, __fmul_rn(v.x, v.x));
            s = __fadd_rn(s, __fmul_rn(v.y, v.y));
            s = __fadd_rn(s, __fmul_rn(v.z, v.z));
            s = __fadd_rn(s, __fmul_rn(v.w, v.w));
        }
        esq_all[k] = s;
    }
    __syncthreads();

    // ---- ||x||^2 per pixel (ascending d, rounded mul then add) ----
    if (t < PT) {
        int pp = t >> 1, comp = t & 1;
        float s = 0.0f;
        #pragma unroll 8
        for (int d = 0; d < DDIM; ++d) {
            float v = ((const float*)&xs[d * 64 + pp])[comp];
            s = __fadd_rn(s, __fmul_rn(v, v));
        }
        xsq[t] = s;
    }

    // warp mapping: 8 pxg x 4 kgg per warp (dedup: 256B x + 64B e per warp-d)
    const int pxg = (t & 7) | ((t >> 4) & 8);   // 0..15, 4 pixel-pairs (8 px) each
    const int kgg = (t >> 3) & 15;              // 0..15, 4 codes each

    float best[8];
    int   bidx[8];
    #pragma unroll
    for (int i = 0; i < 8; ++i) { best[i] = 3.4e38f; bidx[i] = 0; }

    for (int kt = 0; kt < NKT; ++kt) {
        __syncthreads();   // xsq ready (1st iter) / protect es reuse
        // ---- stage e tile DUPLICATED, gmem reads coalesced float4 ----
        #pragma unroll
        for (int it = 0; it < (KT * DDIM / 4) / NTHR; ++it) {  // 4 iters
            int lin = it * NTHR + t;          // 0..1023
            int k   = lin >> 4;               // 0..63
            int d4  = (lin & 15) * 4;         // consecutive lanes -> consecutive d4
            float4 ev = *(const float4*)(emb + (size_t)(kt * KT + k) * DDIM + d4);
            es[(d4 + 0) * 64 + k] = make_float2(ev.x, ev.x);
            es[(d4 + 1) * 64 + k] = make_float2(ev.y, ev.y);
            es[(d4 + 2) * 64 + k] = make_float2(ev.z, ev.z);
            es[(d4 + 3) * 64 + k] = make_float2(ev.w, ev.w);
        }
        __syncthreads();

        // ---- mainloop: 4 LDS.128 (ld.shared.v2.u64) + 16 FFMA2 per d, zero MOVs ----
        uint64_t acc[4][4];
        #pragma unroll
        for (int pp = 0; pp < 4; ++pp)
            #pragma unroll
            for (int j = 0; j < 4; ++j) acc[pp][j] = 0ull;

        const ulonglong2* xsv = (const ulonglong2*)((const uint64_t*)xs + pxg * 4);
        const ulonglong2* esv = (const ulonglong2*)((const uint64_t*)es + kgg * 4);

        #pragma unroll 4
        for (int d = 0; d < DDIM; ++d) {
            const ulonglong2* xp = xsv + d * 32;   // 64 uint64 per d-row = 32 ull2
            const ulonglong2* ep = esv + d * 32;
            ulonglong2 xa = xp[0], xb_ = xp[1];    // 4 pixel-pairs (32B)
            ulonglong2 ea = ep[0], eb = ep[1];     // 4 dup codes   (32B)
            uint64_t x0 = xa.x, x1 = xa.y, x2 = xb_.x, x3 = xb_.y;
            uint64_t e0 = ea.x, e1 = ea.y, e2 = eb.x, e3 = eb.y;
            FMA2(acc[0][0], x0, e0); FMA2(acc[0][1], x0, e1);
            FMA2(acc[0][2], x0, e2); FMA2(acc[0][3], x0, e3);
            FMA2(acc[1][0], x1, e0); FMA2(acc[1][1], x1, e1);
            FMA2(acc[1][2], x1, e2); FMA2(acc[1][3], x1, e3);
            FMA2(acc[2][0], x2, e0); FMA2(acc[2][1], x2, e1);
            FMA2(acc[2][2], x2, e2); FMA2(acc[2][3], x2, e3);
            FMA2(acc[3][0], x3, e0); FMA2(acc[3][1], x3, e1);
            FMA2(acc[3][2], x3, e2); FMA2(acc[3][3], x3, e3);
        }

        // ---- fold: s = fmaf(-2, dot, fl(xsq+esq)); ascending k keeps lowest idx ----
        #pragma unroll
        for (int j = 0; j < 4; ++j) {
            int   k  = kt * KT + kgg * 4 + j;
            float eq = esq_all[k];
            #pragma unroll
            for (int pp = 0; pp < 4; ++pp) {
                float lo, hi;
                asm("mov.b64 {%0, %1}, %2;" : "=f"(lo), "=f"(hi) : "l"(acc[pp][j]));
                float t0 = __fadd_rn(xsq[pxg * 8 + 2 * pp], eq);
                float t1 = __fadd_rn(xsq[pxg * 8 + 2 * pp + 1], eq);
                float s0 = __fmaf_rn(-2.0f, lo, t0);
                float s1 = __fmaf_rn(-2.0f, hi, t1);
                if (s0 < best[2 * pp])     { best[2 * pp]     = s0; bidx[2 * pp]     = k; }
                if (s1 < best[2 * pp + 1]) { best[2 * pp + 1] = s1; bidx[2 * pp + 1] = k; }
            }
        }
    }

    // ---- cross-thread argmin reduction (red arrays overlay xs; xs dead now) ----
    __syncthreads();
    #pragma unroll
    for (int i = 0; i < 8; ++i) {
        red_val[(pxg * 8 + i) * 16 + kgg] = best[i];
        red_idx[(pxg * 8 + i) * 16 + kgg] = bidx[i];
    }
    __syncthreads();
    if (t < PT) {
        float bv = red_val[t * 16 + 0];
        int   bi = red_idx[t * 16 + 0];
        #pragma unroll
        for (int g = 1; g < 16; ++g) {
            float v  = red_val[t * 16 + g];
            int   id = red_idx[t * 16 + g];
            if (v < bv || (v == bv && id < bi)) { bv = v; bi = id; }
        }
        widx[t] = bi;
    }
    __syncthreads();

    // ---- gather + write out[b, c, hw0+p] = emb[widx[p]][c] ----
    float* ob = out + (size_t)b * CHW + hw0;
    #pragma unroll
    for (int it = 0; it < (DDIM * PT) / NTHR; ++it) {
        int lin = it * NTHR + t;
        int c = lin >> 7;
        int p = lin & 127;
        ob[c * HW + p] = emb[(size_t)widx[p] * DDIM + c];
    }
}

extern "C" void kernel_launch(void* const* d_in, const int* in_sizes, int n_in,
                              void* d_out, int out_size)
{
    const float* x   = (const float*)d_in[0];   // [32, 64, 64, 64]
    const float* emb = (const float*)d_in[1];   // [512, 64]
    float* out = (float*)d_out;

    const int HW  = 64 * 64;             // 4096
    const int CHW = DDIM * HW;           // 262144
    const int N   = in_sizes[0] / DDIM;  // 131072 pixels

    cudaFuncSetAttribute(vq_kernel, cudaFuncAttributeMaxDynamicSharedMemorySize,
                         SMEM_BYTES);

    dim3 grid(N / PT);                   // 1024
    dim3 block(NTHR);
    vq_kernel<<<grid, block, SMEM_BYTES>>>(x, emb, out, HW, CHW);
}

// round 15
// speedup vs baseline: 1.5270x; 1.1746x over previous
#include <cuda_runtime.h>
#include <cstdint>

// VectorQuantizer: x [32,64,64,64] fp32, emb [512,64] fp32.
// Per pixel: argmin_k fl(fl(xsq+esq[k]) - 2*dot), dot = sequential ascending-d FMA chain.
// Then out[b,:,h,w] = emb[argmin].
//
// Round 15: empirical binder across ALL rounds = smem BYTES per FMA (~17TB/s eff).
// Minimize B/FMA: dup-x + natural e-pairs, thread tile 8 px x 16 codes:
//   bytes/d = 8px*8B (xdup) + 8pairs*8B (epairs) = 128B per 128 FMA = 1.0 B/FMA
//   (R3 best-so-far was 2.0 B/FMA -> 289us; expect ~x0.8 here)
// Per thread-d: 8 LDS.128 + 64 FFMA2, zero MOVs. acc = 128 regs -> launch_bounds(256,1).
// Block tile 128 px x 256 codes, NKT=2, smem ~131KB, 1 block/SM (8 warps -- fine:
// R10 showed 8 warps hits the same bytes wall as 16).

#define KCODES 512
#define DDIM   64
#define PT     128
#define KT     256
#define NKT    (KCODES / KT)   // 2
#define NTHR   256

// dynamic smem layout (bytes)
#define XD_OFF     0                          // float2 xd[64][128] = 65536  ({x,x} dup)
#define EP_OFF     65536                      // float2 ep[64][128] = 65536  ({e2k,e2k+1})
#define XSQ_OFF    (EP_OFF + 65536)           // float xsq[128]     = 512
#define ESQ_OFF    (XSQ_OFF + 512)            // float esq_all[512] = 2048
#define WIDX_OFF   (ESQ_OFF + 2048)           // int   widx[128]    = 512
#define SMEM_BYTES (WIDX_OFF + 512)           // 134144 <= ~227KB max dyn smem
// reduction arrays overlay xd after the mainloop:
#define RVAL_OFF   XD_OFF                     // float red_val[128][16] = 8192
#define RIDX_OFF   (XD_OFF + 8192)            // int   red_idx[128][16] = 8192

#define FMA2(acc, a, b) \
    asm("fma.rn.f32x2 %0, %1, %2, %0;" : "+l"(acc) : "l"(a), "l"(b))

__global__ __launch_bounds__(NTHR, 1)
void vq_kernel(const float* __restrict__ x,
               const float* __restrict__ emb,
               float* __restrict__ out,
               int HW, int CHW)
{
    extern __shared__ char smem_raw[];
    float2* xd      = (float2*)(smem_raw + XD_OFF);    // xd[d*128 + p]  = {x[p], x[p]}
    float2* ep      = (float2*)(smem_raw + EP_OFF);    // ep[d*128 + kp] = {e[2kp], e[2kp+1]}
    float*  xsq     = (float*)(smem_raw + XSQ_OFF);
    float*  esq_all = (float*)(smem_raw + ESQ_OFF);
    int*    widx    = (int*)(smem_raw + WIDX_OFF);
    float*  red_val = (float*)(smem_raw + RVAL_OFF);
    int*    red_idx = (int*)(smem_raw + RIDX_OFF);

    const int t   = threadIdx.x;
    const int n0  = blockIdx.x * PT;
    const int b   = n0 >> 12;          // HW = 4096; tiles never cross batch
    const int hw0 = n0 & 4095;

    // ---- stage x tile DUPLICATED: xd[c][p] = {x[b,c,hw0+p], same} (coalesced reads) ----
    const float* xb = x + (size_t)b * CHW + hw0;
    #pragma unroll
    for (int it = 0; it < (DDIM * PT) / NTHR; ++it) {   // 32 iters
        int lin = it * NTHR + t;
        int c = lin >> 7;
        int p = lin & 127;
        float v = xb[c * HW + p];
        xd[c * 128 + p] = make_float2(v, v);
    }

    // ---- esq for ALL 512 codes, once (ascending d, rounded mul then add) ----
    #pragma unroll
    for (int kk = 0; kk < 2; ++kk) {
        int k = t * 2 + kk;
        const float4* er = (const float4*)(emb + (size_t)k * DDIM);
        float s = 0.0f;
        #pragma unroll
        for (int q = 0; q < DDIM / 4; ++q) {
            float4 v = er[q];
            s = __fadd_rn(s, __fmul_rn(v.x, v.x));
            s = __fadd_rn(s, __fmul_rn(v.y, v.y));
            s = __fadd_rn(s, __fmul_rn(v.z, v.z));
            s = __fadd_rn(s, __fmul_rn(v.w, v.w));
        }
        esq_all[k] = s;
    }
    __syncthreads();

    // ---- ||x||^2 per pixel (ascending d, rounded mul then add) ----
    if (t < PT) {
        float s = 0.0f;
        #pragma unroll 8
        for (int d = 0; d < DDIM; ++d) {
            float v = xd[d * 128 + t].x;
            s = __fadd_rn(s, __fmul_rn(v, v));
        }
        xsq[t] = s;
    }

    const int pxg = t & 15;    // 16 groups x 8 pixels
    const int kgg = t >> 4;    // 16 groups x 16 codes (8 pairs)

    float best[8];
    int   bidx[8];
    #pragma unroll
    for (int i = 0; i < 8; ++i) { best[i] = 3.4e38f; bidx[i] = 0; }

    for (int kt = 0; kt < NKT; ++kt) {
        __syncthreads();   // xsq/xd ready (1st iter) / protect ep reuse
        // ---- stage e tile as natural pairs: ep[d][kp] = {e[2kp], e[2kp+1]} ----
        // gmem reads coalesced float4 along d within each code row.
        #pragma unroll
        for (int it = 0; it < (KT * DDIM / 4) / NTHR; ++it) {  // 16 iters
            int lin = it * NTHR + t;          // 0..4095
            int k   = lin >> 4;               // 0..255
            int d4  = (lin & 15) * 4;
            float4 ev = *(const float4*)(emb + (size_t)(kt * KT + k) * DDIM + d4);
            int kp = k >> 1, half = k & 1;
            ((float*)&ep[(d4 + 0) * 128 + kp])[half] = ev.x;
            ((float*)&ep[(d4 + 1) * 128 + kp])[half] = ev.y;
            ((float*)&ep[(d4 + 2) * 128 + kp])[half] = ev.z;
            ((float*)&ep[(d4 + 3) * 128 + kp])[half] = ev.w;
        }
        __syncthreads();

        // ---- mainloop: 8 LDS.128 + 64 FFMA2 per d, zero MOVs ----
        // acc[i][j] = {sum x_i*e_{2j}, sum x_i*e_{2j+1}}
        uint64_t acc[8][8];
        #pragma unroll
        for (int i = 0; i < 8; ++i)
            #pragma unroll
            for (int j = 0; j < 8; ++j) acc[i][j] = 0ull;

        const ulonglong2* xv = (const ulonglong2*)((const uint64_t*)xd + pxg * 8);
        const ulonglong2* evp = (const ulonglong2*)((const uint64_t*)ep + kgg * 8);

        #pragma unroll 1
        for (int d = 0; d < DDIM; ++d) {
            const ulonglong2* xp = xv + d * 64;    // row = 128 ull = 64 ull2
            const ulonglong2* epr = evp + d * 64;
            ulonglong2 xa = xp[0], xb2_ = xp[1], xc = xp[2], xd2 = xp[3];
            ulonglong2 ea = epr[0], eb = epr[1], ec = epr[2], ed = epr[3];
            uint64_t x0 = xa.x,  x1 = xa.y,  x2 = xb2_.x, x3 = xb2_.y;
            uint64_t x4 = xc.x,  x5 = xc.y,  x6 = xd2.x,  x7 = xd2.y;
            uint64_t e0 = ea.x,  e1 = ea.y,  e2 = eb.x,   e3 = eb.y;
            uint64_t e4 = ec.x,  e5 = ec.y,  e6 = ed.x,   e7 = ed.y;
            FMA2(acc[0][0], x0, e0); FMA2(acc[0][1], x0, e1);
            FMA2(acc[0][2], x0, e2); FMA2(acc[0][3], x0, e3);
            FMA2(acc[0][4], x0, e4); FMA2(acc[0][5], x0, e5);
            FMA2(acc[0][6], x0, e6); FMA2(acc[0][7], x0, e7);
            FMA2(acc[1][0], x1, e0); FMA2(acc[1][1], x1, e1);
            FMA2(acc[1][2], x1, e2); FMA2(acc[1][3], x1, e3);
            FMA2(acc[1][4], x1, e4); FMA2(acc[1][5], x1, e5);
            FMA2(acc[1][6], x1, e6); FMA2(acc[1][7], x1, e7);
            FMA2(acc[2][0], x2, e0); FMA2(acc[2][1], x2, e1);
            FMA2(acc[2][2], x2, e2); FMA2(acc[2][3], x2, e3);
            FMA2(acc[2][4], x2, e4); FMA2(acc[2][5], x2, e5);
            FMA2(acc[2][6], x2, e6); FMA2(acc[2][7], x2, e7);
            FMA2(acc[3][0], x3, e0); FMA2(acc[3][1], x3, e1);
            FMA2(acc[3][2], x3, e2); FMA2(acc[3][3], x3, e3);
            FMA2(acc[3][4], x3, e4); FMA2(acc[3][5], x3, e5);
            FMA2(acc[3][6], x3, e6); FMA2(acc[3][7], x3, e7);
            FMA2(acc[4][0], x4, e0); FMA2(acc[4][1], x4, e1);
            FMA2(acc[4][2], x4, e2); FMA2(acc[4][3], x4, e3);
            FMA2(acc[4][4], x4, e4); FMA2(acc[4][5], x4, e5);
            FMA2(acc[4][6], x4, e6); FMA2(acc[4][7], x4, e7);
            FMA2(acc[5][0], x5, e0); FMA2(acc[5][1], x5, e1);
            FMA2(acc[5][2], x5, e2); FMA2(acc[5][3], x5, e3);
            FMA2(acc[5][4], x5, e4); FMA2(acc[5][5], x5, e5);
            FMA2(acc[5][6], x5, e6); FMA2(acc[5][7], x5, e7);
            FMA2(acc[6][0], x6, e0); FMA2(acc[6][1], x6, e1);
            FMA2(acc[6][2], x6, e2); FMA2(acc[6][3], x6, e3);
            FMA2(acc[6][4], x6, e4); FMA2(acc[6][5], x6, e5);
            FMA2(acc[6][6], x6, e6); FMA2(acc[6][7], x6, e7);
            FMA2(acc[7][0], x7, e0); FMA2(acc[7][1], x7, e1);
            FMA2(acc[7][2], x7, e2); FMA2(acc[7][3], x7, e3);
            FMA2(acc[7][4], x7, e4); FMA2(acc[7][5], x7, e5);
            FMA2(acc[7][6], x7, e6); FMA2(acc[7][7], x7, e7);
        }

        // ---- fold: s = fmaf(-2, dot, fl(xsq+esq)); ascending k keeps lowest idx ----
        #pragma unroll
        for (int j = 0; j < 8; ++j) {
            int   k0  = kt * KT + kgg * 16 + 2 * j;
            float eq0 = esq_all[k0];
            float eq1 = esq_all[k0 + 1];
            #pragma unroll
            for (int i = 0; i < 8; ++i) {
                float lo, hi;
                asm("mov.b64 {%0, %1}, %2;" : "=f"(lo), "=f"(hi) : "l"(acc[i][j]));
                float xq = xsq[pxg * 8 + i];
                float s0 = __fmaf_rn(-2.0f, lo, __fadd_rn(xq, eq0));
                float s1 = __fmaf_rn(-2.0f, hi, __fadd_rn(xq, eq1));
                if (s0 < best[i]) { best[i] = s0; bidx[i] = k0; }
                if (s1 < best[i]) { best[i] = s1; bidx[i] = k0 + 1; }
            }
        }
    }

    // ---- cross-thread argmin reduction (red arrays overlay xd; xd dead now) ----
    __syncthreads();
    #pragma unroll
    for (int i = 0; i < 8; ++i) {
        red_val[(pxg * 8 + i) * 16 + kgg] = best[i];
        red_idx[(pxg * 8 + i) * 16 + kgg] = bidx[i];
    }
    __syncthreads();
    if (t < PT) {
        float bv = red_val[t * 16 + 0];
        int   bi = red_idx[t * 16 + 0];
        #pragma unroll
        for (int g = 1; g < 16; ++g) {
            float v  = red_val[t * 16 + g];
            int   id = red_idx[t * 16 + g];
            if (v < bv || (v == bv && id < bi)) { bv = v; bi = id; }
        }
        widx[t] = bi;
    }
    __syncthreads();

    // ---- gather + write out[b, c, hw0+p] = emb[widx[p]][c] ----
    float* ob = out + (size_t)b * CHW + hw0;
    #pragma unroll
    for (int it = 0; it < (DDIM * PT) / NTHR; ++it) {
        int lin = it * NTHR + t;
        int c = lin >> 7;
        int p = lin & 127;
        ob[c * HW + p] = emb[(size_t)widx[p] * DDIM + c];
    }
}

extern "C" void kernel_launch(void* const* d_in, const int* in_sizes, int n_in,
                              void* d_out, int out_size)
{
    const float* x   = (const float*)d_in[0];   // [32, 64, 64, 64]
    const float* emb = (const float*)d_in[1];   // [512, 64]
    float* out = (float*)d_out;

    const int HW  = 64 * 64;             // 4096
    const int CHW = DDIM * HW;           // 262144
    const int N   = in_sizes[0] / DDIM;  // 131072 pixels

    cudaFuncSetAttribute(vq_kernel, cudaFuncAttributeMaxDynamicSharedMemorySize,
                         SMEM_BYTES);

    dim3 grid(N / PT);                   // 1024
    dim3 block(NTHR);
    vq_kernel<<<grid, block, SMEM_BYTES>>>(x, emb, out, HW, CHW);
}